// round 16
// baseline (speedup 1.0000x reference)
#include <cuda_runtime.h>
#include <cuda_bf16.h>
#include <mma.h>

using namespace nvcuda;

#define N_USERS 100000
#define N_ITEMS 50000
#define N_NODES 150000
#define EMB     128
#define EMB4    32
#define NNZ     2400000
#define ALPHA   0.25f
#define SCAN_NB ((N_NODES + 255) / 256)

// ---------------- device scratch (static, no runtime allocation) ------------
// g_cnt zero-on-entry invariant: zeroed at load; k_scan re-zeroes after read.
// g_blkdesc reset each call by k_hist (ordered before k_scan on the stream).
__device__ __align__(16) __nv_bfloat16  g_embh[3][(size_t)N_NODES * EMB]; // bf16 layers 0..2
__device__ __align__(16) __nv_bfloat16  g_whi[EMB * EMB];                 // W hi (bf16)
__device__ __align__(16) __nv_bfloat16  g_wlo[EMB * EMB];                 // W lo (bf16)
__device__ int   g_cnt[N_NODES];
__device__ int   g_off[N_NODES + 1];
__device__ int   g_fill[N_NODES];
__device__ unsigned long long g_blkdesc[SCAN_NB]; // hi32: 0 inval,1 agg,2 incl; lo32 sum
__device__ uint2 g_edge[NNZ];                     // (col*16 pre-scaled, float-bits of val)

// ---------------- helpers ----------------------------------------------------
__device__ __forceinline__ void fma_bf16x8(uint4 u, float v, float* acc) {
    __nv_bfloat162 b0 = *reinterpret_cast<const __nv_bfloat162*>(&u.x);
    __nv_bfloat162 b1 = *reinterpret_cast<const __nv_bfloat162*>(&u.y);
    __nv_bfloat162 b2 = *reinterpret_cast<const __nv_bfloat162*>(&u.z);
    __nv_bfloat162 b3 = *reinterpret_cast<const __nv_bfloat162*>(&u.w);
    float2 f0 = __bfloat1622float2(b0);
    float2 f1 = __bfloat1622float2(b1);
    float2 f2 = __bfloat1622float2(b2);
    float2 f3 = __bfloat1622float2(b3);
    acc[0] = fmaf(v, f0.x, acc[0]); acc[1] = fmaf(v, f0.y, acc[1]);
    acc[2] = fmaf(v, f1.x, acc[2]); acc[3] = fmaf(v, f1.y, acc[3]);
    acc[4] = fmaf(v, f2.x, acc[4]); acc[5] = fmaf(v, f2.y, acc[5]);
    acc[6] = fmaf(v, f3.x, acc[6]); acc[7] = fmaf(v, f3.y, acc[7]);
}

__device__ __forceinline__ void bf16x8_to_f8(uint4 u, float* f) {
    __nv_bfloat162 b0 = *reinterpret_cast<const __nv_bfloat162*>(&u.x);
    __nv_bfloat162 b1 = *reinterpret_cast<const __nv_bfloat162*>(&u.y);
    __nv_bfloat162 b2 = *reinterpret_cast<const __nv_bfloat162*>(&u.z);
    __nv_bfloat162 b3 = *reinterpret_cast<const __nv_bfloat162*>(&u.w);
    float2 f0 = __bfloat1622float2(b0);
    float2 f1 = __bfloat1622float2(b1);
    float2 f2 = __bfloat1622float2(b2);
    float2 f3 = __bfloat1622float2(b3);
    f[0] = f0.x; f[1] = f0.y; f[2] = f1.x; f[3] = f1.y;
    f[4] = f2.x; f[5] = f2.y; f[6] = f3.x; f[7] = f3.y;
}

__device__ __forceinline__ uint4 pack_bf16x8(const float* a) {
    uint4 r;
    __nv_bfloat162 h0 = __floats2bfloat162_rn(a[0], a[1]);
    __nv_bfloat162 h1 = __floats2bfloat162_rn(a[2], a[3]);
    __nv_bfloat162 h2 = __floats2bfloat162_rn(a[4], a[5]);
    __nv_bfloat162 h3 = __floats2bfloat162_rn(a[6], a[7]);
    r.x = *reinterpret_cast<const unsigned*>(&h0);
    r.y = *reinterpret_cast<const unsigned*>(&h1);
    r.z = *reinterpret_cast<const unsigned*>(&h2);
    r.w = *reinterpret_cast<const unsigned*>(&h3);
    return r;
}

__device__ __forceinline__ uint2 pack_bf16x4(float4 a) {
    uint2 r;
    __nv_bfloat162 h0 = __floats2bfloat162_rn(a.x, a.y);
    __nv_bfloat162 h1 = __floats2bfloat162_rn(a.z, a.w);
    r.x = *reinterpret_cast<const unsigned*>(&h0);
    r.y = *reinterpret_cast<const unsigned*>(&h1);
    return r;
}

// cp.async helpers (16B, L1-bypass)
__device__ __forceinline__ void cp16(unsigned sa, const void* g) {
    asm volatile("cp.async.cg.shared.global [%0], [%1], 16;" :: "r"(sa), "l"(g));
}
#define CP_COMMIT() asm volatile("cp.async.commit_group;")
#define CP_WAIT(n)  asm volatile("cp.async.wait_group %0;" :: "n"(n))

// ---------------- hist: edge histogram + blkdesc reset + W split ------------
__global__ void k_hist(const int* __restrict__ rows, const float4* __restrict__ W4) {
    int i = blockIdx.x * blockDim.x + threadIdx.x;
    if (i < SCAN_NB) g_blkdesc[i] = 0ull;
    if (i < 4096) {                    // one-time W hi/lo split (128x128 fp32)
        float4 w = W4[i];
        float wv[4] = {w.x, w.y, w.z, w.w};
        float hv[4], lv[4];
#pragma unroll
        for (int q = 0; q < 4; q++) {
            __nv_bfloat16 h = __float2bfloat16(wv[q]);
            hv[q] = __bfloat162float(h);
            lv[q] = wv[q] - hv[q];
        }
        reinterpret_cast<uint2*>(g_whi)[i] =
            pack_bf16x4(make_float4(hv[0], hv[1], hv[2], hv[3]));
        reinterpret_cast<uint2*>(g_wlo)[i] =
            pack_bf16x4(make_float4(lv[0], lv[1], lv[2], lv[3]));
    }
    if (i < NNZ) atomicAdd(&g_cnt[rows[i]], 1);   // g_cnt zero on entry (invariant)
}

// ---------------- single-pass scan (decoupled lookback) ----------------------
__global__ void __launch_bounds__(256) k_scan() {
    __shared__ int s[256];
    __shared__ int s_base;
    int tid = threadIdx.x, bid = blockIdx.x;
    int gid = bid * 256 + tid;
    int v = (gid < N_NODES) ? g_cnt[gid] : 0;
    if (gid < N_NODES) g_cnt[gid] = 0;            // restore zero invariant
    s[tid] = v;
    __syncthreads();
#pragma unroll
    for (int d = 1; d < 256; d <<= 1) {
        int t = (tid >= d) ? s[tid - d] : 0;
        __syncthreads();
        if (tid >= d) s[tid] += t;
        __syncthreads();
    }
    int incl = s[tid];
    int agg  = s[255];
    if (tid == 0) {
        unsigned long long w = ((bid == 0 ? 2ULL : 1ULL) << 32) | (unsigned)agg;
        atomicExch(&g_blkdesc[bid], w);
        if (bid == 0) s_base = 0;
    }
    if (bid > 0 && tid < 32) {
        int lane = tid;
        int exc = 0;
        int look = bid - 1;
        while (true) {
            int idx = look - lane;
            unsigned long long w;
            if (idx >= 0) {
                do { w = *(volatile unsigned long long*)&g_blkdesc[idx]; }
                while ((unsigned)(w >> 32) == 0u);
            } else {
                w = (2ULL << 32);
            }
            unsigned st = (unsigned)(w >> 32);
            int val = (int)(unsigned)w;
            unsigned bal = __ballot_sync(0xffffffffu, st == 2u);
            int first = __ffs(bal) - 1;
            int contrib = bal ? ((lane <= first) ? val : 0) : val;
#pragma unroll
            for (int o = 16; o; o >>= 1) contrib += __shfl_down_sync(0xffffffffu, contrib, o);
            contrib = __shfl_sync(0xffffffffu, contrib, 0);
            exc += contrib;
            if (bal) break;
            look -= 32;
        }
        if (lane == 0) {
            atomicExch(&g_blkdesc[bid], (2ULL << 32) | (unsigned)(exc + agg));
            s_base = exc;
        }
    }
    __syncthreads();
    int base = s_base;
    if (gid < N_NODES) {
        int o = base + incl - v;
        g_off[gid]  = o;
        g_fill[gid] = o;
    }
    if (gid == 0) g_off[N_NODES] = NNZ;
}

// ---------------- conv + scatter fused (post-scan) ---------------------------
__global__ void k_convscatter(const float4* __restrict__ ue, const float4* __restrict__ ie,
                              const int* __restrict__ rows, const int* __restrict__ cols,
                              const float* __restrict__ vals) {
    int i = blockIdx.x * blockDim.x + threadIdx.x;
    if (i < NNZ) {
        int p = atomicAdd(&g_fill[rows[i]], 1);
        g_edge[p] = make_uint2((unsigned)cols[i] * 16u, __float_as_uint(vals[i]));
    }
    if (i >= N_NODES * EMB4) return;
    int node = i >> 5;
    float4 v = (node < N_USERS) ? ue[i] : ie[i - N_USERS * EMB4];
    reinterpret_cast<uint2*>(g_embh[0])[i] = pack_bf16x4(v);
}

// ---------------- SpMM: warp/row, cp.async double-buffered gather -----------
// Per warp: 2 stages x 8 edges x 256B smem slice; edge descriptors prefetched
// 2 batches ahead in registers. Lanes 0-15 even edges, 16-31 odd (R7 pairing).
__global__ void __launch_bounds__(256) k_spmm(int layer) {
    __shared__ __align__(16) char sbuf[8][2][8][256];   // 32 KB
    int wwarp = threadIdx.x >> 5;
    int gw    = (blockIdx.x * 256 + threadIdx.x) >> 5;
    int lane  = threadIdx.x & 31;
    if (gw >= N_NODES) return;
    int half  = lane >> 4;
    unsigned hl = lane & 15;
    const char* srcb = reinterpret_cast<const char*>(g_embh[layer]);
    const uint4* src = reinterpret_cast<const uint4*>(g_embh[layer]);
    int beg = g_off[gw], end = g_off[gw + 1];
    int cnt = end - beg;
    int nfull = cnt >> 3;
    float acc[8] = {0.f, 0.f, 0.f, 0.f, 0.f, 0.f, 0.f, 0.f};
    uint2 edA[4], edB[4];

    if (nfull > 0) {
#pragma unroll
        for (int p = 0; p < 4; p++) edA[p] = __ldg(&g_edge[beg + 2 * p + half]);
#pragma unroll
        for (int p = 0; p < 4; p++)
            cp16((unsigned)__cvta_generic_to_shared(&sbuf[wwarp][0][2 * p + half][hl * 16]),
                 srcb + (size_t)(edA[p].x + hl) * 16u);
        CP_COMMIT();
    }
    if (nfull > 1) {
#pragma unroll
        for (int p = 0; p < 4; p++) edB[p] = __ldg(&g_edge[beg + 8 + 2 * p + half]);
#pragma unroll
        for (int p = 0; p < 4; p++)
            cp16((unsigned)__cvta_generic_to_shared(&sbuf[wwarp][1][2 * p + half][hl * 16]),
                 srcb + (size_t)(edB[p].x + hl) * 16u);
        CP_COMMIT();
    }
    int b = 0;
    while (b < nfull) {
        // ---- stage 0 (edA) ----
        if (b + 1 < nfull) { CP_WAIT(1); } else { CP_WAIT(0); }
#pragma unroll
        for (int p = 0; p < 4; p++) {
            uint4 x = *reinterpret_cast<const uint4*>(&sbuf[wwarp][0][2 * p + half][hl * 16]);
            fma_bf16x8(x, __uint_as_float(edA[p].y), acc);
        }
        if (b + 2 < nfull) {
            int eb = beg + 8 * (b + 2);
#pragma unroll
            for (int p = 0; p < 4; p++) edA[p] = __ldg(&g_edge[eb + 2 * p + half]);
#pragma unroll
            for (int p = 0; p < 4; p++)
                cp16((unsigned)__cvta_generic_to_shared(&sbuf[wwarp][0][2 * p + half][hl * 16]),
                     srcb + (size_t)(edA[p].x + hl) * 16u);
            CP_COMMIT();
        }
        b++;
        if (b >= nfull) break;
        // ---- stage 1 (edB) ----
        if (b + 1 < nfull) { CP_WAIT(1); } else { CP_WAIT(0); }
#pragma unroll
        for (int p = 0; p < 4; p++) {
            uint4 x = *reinterpret_cast<const uint4*>(&sbuf[wwarp][1][2 * p + half][hl * 16]);
            fma_bf16x8(x, __uint_as_float(edB[p].y), acc);
        }
        if (b + 2 < nfull) {
            int eb = beg + 8 * (b + 2);
#pragma unroll
            for (int p = 0; p < 4; p++) edB[p] = __ldg(&g_edge[eb + 2 * p + half]);
#pragma unroll
            for (int p = 0; p < 4; p++)
                cp16((unsigned)__cvta_generic_to_shared(&sbuf[wwarp][1][2 * p + half][hl * 16]),
                     srcb + (size_t)(edB[p].x + hl) * 16u);
            CP_COMMIT();
        }
        b++;
    }
    // ---- tail: remaining cnt & 7 edges, direct LDG (R7 path) ----
    int e = beg + 8 * nfull;
    for (; e + 2 <= end; e += 2) {
        uint2 ed = __ldg(&g_edge[e + half]);
        uint4 x  = src[ed.x + hl];
        fma_bf16x8(x, __uint_as_float(ed.y), acc);
    }
    if (e < end) {
        uint2 ed = __ldg(&g_edge[e]);
        uint4 x  = src[ed.x + hl];
        float v  = half ? 0.f : __uint_as_float(ed.y);
        fma_bf16x8(x, v, acc);
    }
#pragma unroll
    for (int d = 0; d < 8; d++)
        acc[d] += __shfl_xor_sync(0xffffffffu, acc[d], 16);
    if (half == 0)
        reinterpret_cast<uint4*>(g_embh[layer + 1])[(unsigned)gw * 16u + hl] = pack_bf16x8(acc);
}

// ---------------- final: SpMM layer 2->3 fused with combine + outputs -------
// (R7 gather core kept here deliberately — containment for the cp.async test)
#define O2_4 ((size_t)N_NODES * EMB4)                       // masked_user
#define O3_4 (O2_4 + (size_t)N_USERS * EMB4)                // predicted
#define O4_4 (O3_4 + (size_t)N_USERS * EMB4)                // mask

__global__ void __launch_bounds__(256) k_final(const float4* __restrict__ ue,
                                               const float4* __restrict__ ie,
                                               const float4* __restrict__ mask,
                                               float4* __restrict__ out) {
    int gw   = (blockIdx.x * 256 + threadIdx.x) >> 5;
    int lane = threadIdx.x & 31;
    if (gw >= N_NODES) return;
    int half = lane >> 4;
    unsigned hl = lane & 15;
    const uint4* __restrict__ src = reinterpret_cast<const uint4*>(g_embh[2]);
    int beg = g_off[gw], end = g_off[gw + 1];
    float acc[8] = {0.f, 0.f, 0.f, 0.f, 0.f, 0.f, 0.f, 0.f};
    int e = beg;
    for (; e + 8 <= end; e += 8) {
        uint2 ed[4]; uint4 x[4];
#pragma unroll
        for (int p = 0; p < 4; p++) ed[p] = __ldg(&g_edge[e + 2 * p + half]);
#pragma unroll
        for (int p = 0; p < 4; p++) x[p] = src[ed[p].x + hl];
#pragma unroll
        for (int p = 0; p < 4; p++) fma_bf16x8(x[p], __uint_as_float(ed[p].y), acc);
    }
    for (; e + 2 <= end; e += 2) {
        uint2 ed = __ldg(&g_edge[e + half]);
        uint4 x  = src[ed.x + hl];
        fma_bf16x8(x, __uint_as_float(ed.y), acc);
    }
    if (e < end) {
        uint2 ed = __ldg(&g_edge[e]);
        uint4 x  = src[ed.x + hl];
        float v  = half ? 0.f : __uint_as_float(ed.y);
        fma_bf16x8(x, v, acc);
    }
#pragma unroll
    for (int d = 0; d < 8; d++)
        acc[d] += __shfl_xor_sync(0xffffffffu, acc[d], 16);
    if (half) return;

    unsigned g16 = (unsigned)gw * 16u + hl;
    size_t   g32 = (size_t)gw * 32u + 2u * hl;
    float l0[8], l1[8], l2[8];
    {
        float4 a0, a1;
        if (gw < N_USERS) { a0 = ue[g32]; a1 = ue[g32 + 1]; }
        else { size_t o = g32 - (size_t)N_USERS * 32u; a0 = ie[o]; a1 = ie[o + 1]; }
        l0[0]=a0.x; l0[1]=a0.y; l0[2]=a0.z; l0[3]=a0.w;
        l0[4]=a1.x; l0[5]=a1.y; l0[6]=a1.z; l0[7]=a1.w;
    }
    bf16x8_to_f8(reinterpret_cast<const uint4*>(g_embh[1])[g16], l1);
    bf16x8_to_f8(reinterpret_cast<const uint4*>(g_embh[2])[g16], l2);
    float comb[8];
#pragma unroll
    for (int d = 0; d < 8; d++)
        comb[d] = ALPHA * (l0[d] + l1[d] + l2[d] + acc[d]);
    float4 c0 = make_float4(comb[0], comb[1], comb[2], comb[3]);
    float4 c1 = make_float4(comb[4], comb[5], comb[6], comb[7]);
    out[g32]     = c0;
    out[g32 + 1] = c1;
    if (gw < N_USERS) {
        float4 m0 = mask[g32], m1 = mask[g32 + 1];
        out[O2_4 + g32]     = make_float4(c0.x*m0.x, c0.y*m0.y, c0.z*m0.z, c0.w*m0.w);
        out[O2_4 + g32 + 1] = make_float4(c1.x*m1.x, c1.y*m1.y, c1.z*m1.z, c1.w*m1.w);
        out[O4_4 + g32]     = m0;
        out[O4_4 + g32 + 1] = m1;
    }
}

// ---------------- GEMM: bf16-split tensor cores, fully smem-staged ----------
#define WLD 136
#define CLD 132
__global__ void __launch_bounds__(256) k_gemm_tc(const float* __restrict__ A,
                                                 const float* __restrict__ bias,
                                                 float* __restrict__ C, int M) {
    extern __shared__ __align__(16) char smem_raw[];
    __nv_bfloat16* Whi = reinterpret_cast<__nv_bfloat16*>(smem_raw);
    __nv_bfloat16* Wlo = Whi + 128 * WLD;
    __nv_bfloat16* Ahi = Wlo + 128 * WLD;
    __nv_bfloat16* Alo = Ahi + 128 * WLD;
    int tid = threadIdx.x;
    int wid = tid >> 5;
    int m_base = blockIdx.x * 128;
    int wm = wid & 3;
    int wn = wid >> 2;

#pragma unroll
    for (int p = 0; p < 8; p++) {
        int i = tid + p * 256;
        int r = i >> 4, c8 = (i & 15) * 8;
        int gidx = r * 16 + (i & 15);
        *reinterpret_cast<uint4*>(&Whi[r * WLD + c8]) = reinterpret_cast<const uint4*>(g_whi)[gidx];
        *reinterpret_cast<uint4*>(&Wlo[r * WLD + c8]) = reinterpret_cast<const uint4*>(g_wlo)[gidx];
    }
#pragma unroll
    for (int p = 0; p < 16; p++) {
        int i = (tid + p * 256) * 4;
        int r = i >> 7, c = i & 127;
        int gm = m_base + r;
        float4 a = (gm < M) ? *reinterpret_cast<const float4*>(&A[(size_t)gm * 128 + c])
                            : make_float4(0.f, 0.f, 0.f, 0.f);
        float av[4] = {a.x, a.y, a.z, a.w};
#pragma unroll
        for (int q = 0; q < 4; q++) {
            __nv_bfloat16 h = __float2bfloat16(av[q]);
            Ahi[r * WLD + c + q] = h;
            Alo[r * WLD + c + q] = __float2bfloat16(av[q] - __bfloat162float(h));
        }
    }
    __syncthreads();

    wmma::fragment<wmma::accumulator, 16, 16, 16, float> acc[2][4];
#pragma unroll
    for (int im = 0; im < 2; im++)
#pragma unroll
        for (int jn = 0; jn < 4; jn++) wmma::fill_fragment(acc[im][jn], 0.0f);

#pragma unroll
    for (int k = 0; k < 128; k += 16) {
        wmma::fragment<wmma::matrix_a, 16, 16, 16, __nv_bfloat16, wmma::row_major> ahi[2], alo[2];
#pragma unroll
        for (int im = 0; im < 2; im++) {
            int row = wm * 32 + im * 16;
            wmma::load_matrix_sync(ahi[im], Ahi + row * WLD + k, WLD);
            wmma::load_matrix_sync(alo[im], Alo + row * WLD + k, WLD);
        }
#pragma unroll
        for (int jn = 0; jn < 4; jn++) {
            wmma::fragment<wmma::matrix_b, 16, 16, 16, __nv_bfloat16, wmma::row_major> bhi, blo;
            int bof = k * WLD + wn * 64 + jn * 16;
            wmma::load_matrix_sync(bhi, Whi + bof, WLD);
            wmma::load_matrix_sync(blo, Wlo + bof, WLD);
#pragma unroll
            for (int im = 0; im < 2; im++) {
                wmma::mma_sync(acc[im][jn], ahi[im], bhi, acc[im][jn]);
                wmma::mma_sync(acc[im][jn], ahi[im], blo, acc[im][jn]);
                wmma::mma_sync(acc[im][jn], alo[im], bhi, acc[im][jn]);
            }
        }
    }
    __syncthreads();
    float* cs = reinterpret_cast<float*>(smem_raw);
#pragma unroll
    for (int im = 0; im < 2; im++)
#pragma unroll
        for (int jn = 0; jn < 4; jn++)
            wmma::store_matrix_sync(&cs[(wm * 32 + im * 16) * CLD + wn * 64 + jn * 16],
                                    acc[im][jn], CLD, wmma::mem_row_major);
    __syncthreads();
#pragma unroll
    for (int q = 0; q < 16; q++) {
        int i = tid + q * 256;
        int r = i >> 5, c4 = (i & 31) * 4;
        int gm = m_base + r;
        if (gm < M) {
            float4 v  = *reinterpret_cast<float4*>(&cs[r * CLD + c4]);
            float4 b4 = *reinterpret_cast<const float4*>(&bias[c4]);
            v.x = fmaxf(v.x + b4.x, 0.f); v.y = fmaxf(v.y + b4.y, 0.f);
            v.z = fmaxf(v.z + b4.z, 0.f); v.w = fmaxf(v.w + b4.w, 0.f);
            *reinterpret_cast<float4*>(&C[(size_t)gm * 128 + c4]) = v;
        }
    }
}

// ---------------- launch -----------------------------------------------------
extern "C" void kernel_launch(void* const* d_in, const int* in_sizes, int n_in,
                              void* d_out, int out_size) {
    const float* ue   = (const float*)d_in[0];
    const float* ie   = (const float*)d_in[1];
    const int*   rows = (const int*)  d_in[2];
    const int*   cols = (const int*)  d_in[3];
    const float* vals = (const float*)d_in[4];
    const float* mask = (const float*)d_in[5];
    const float* W    = (const float*)d_in[6];
    const float* bias = (const float*)d_in[7];
    float* out = (float*)d_out;

    const int GEMM_SMEM = 4 * 128 * WLD * (int)sizeof(__nv_bfloat16); // 139264 B
    cudaFuncSetAttribute(k_gemm_tc, cudaFuncAttributeMaxDynamicSharedMemorySize, GEMM_SMEM);

    int nthr = N_NODES * EMB4;  // 4.8M
    k_hist<<<(NNZ + 255) / 256, 256>>>(rows, (const float4*)W);
    k_scan<<<SCAN_NB, 256>>>();
    k_convscatter<<<(nthr + 255) / 256, 256>>>((const float4*)ue, (const float4*)ie,
                                               rows, cols, vals);
    k_spmm<<<(N_NODES * 32 + 255) / 256, 256>>>(0);
    k_spmm<<<(N_NODES * 32 + 255) / 256, 256>>>(1);
    k_final<<<(N_NODES * 32 + 255) / 256, 256>>>((const float4*)ue, (const float4*)ie,
                                                 (const float4*)mask, (float4*)out);

    const float* Amasked = out + (size_t)N_NODES * EMB;   // masked_user (fp32)
    float* Cpred = out + (size_t)N_NODES * EMB + (size_t)N_USERS * EMB;
    k_gemm_tc<<<(N_USERS + 127) / 128, 256, GEMM_SMEM>>>(Amasked, bias, Cpred, N_USERS);
}

// round 17
// speedup vs baseline: 1.1053x; 1.1053x over previous
#include <cuda_runtime.h>
#include <cuda_bf16.h>
#include <mma.h>

using namespace nvcuda;

#define N_USERS 100000
#define N_ITEMS 50000
#define N_NODES 150000
#define EMB     128
#define EMB4    32
#define NNZ     2400000
#define ALPHA   0.25f
#define SCAN_NB ((N_NODES + 255) / 256)

// ---------------- device scratch (static, no runtime allocation) ------------
// g_cnt zero-on-entry invariant: zeroed at load; k_scan re-zeroes after read.
// g_blkdesc reset each call by k_hist (ordered before k_scan on the stream).
__device__ __align__(16) __nv_bfloat16  g_embh[3][(size_t)N_NODES * EMB]; // bf16 layers 0..2
__device__ __align__(16) __nv_bfloat16  g_whi[EMB * EMB];                 // W hi (bf16)
__device__ __align__(16) __nv_bfloat16  g_wlo[EMB * EMB];                 // W lo (bf16)
__device__ int   g_cnt[N_NODES];
__device__ int   g_off[N_NODES + 1];
__device__ int   g_fill[N_NODES];
__device__ unsigned long long g_blkdesc[SCAN_NB]; // hi32: 0 inval,1 agg,2 incl; lo32 sum
__device__ uint2 g_edge[NNZ];                     // (col*16 pre-scaled, float-bits of val)

// ---------------- helpers (R7 gather core: proven optimum, frozen) ----------
__device__ __forceinline__ void fma_bf16x8(uint4 u, float v, float* acc) {
    __nv_bfloat162 b0 = *reinterpret_cast<const __nv_bfloat162*>(&u.x);
    __nv_bfloat162 b1 = *reinterpret_cast<const __nv_bfloat162*>(&u.y);
    __nv_bfloat162 b2 = *reinterpret_cast<const __nv_bfloat162*>(&u.z);
    __nv_bfloat162 b3 = *reinterpret_cast<const __nv_bfloat162*>(&u.w);
    float2 f0 = __bfloat1622float2(b0);
    float2 f1 = __bfloat1622float2(b1);
    float2 f2 = __bfloat1622float2(b2);
    float2 f3 = __bfloat1622float2(b3);
    acc[0] = fmaf(v, f0.x, acc[0]); acc[1] = fmaf(v, f0.y, acc[1]);
    acc[2] = fmaf(v, f1.x, acc[2]); acc[3] = fmaf(v, f1.y, acc[3]);
    acc[4] = fmaf(v, f2.x, acc[4]); acc[5] = fmaf(v, f2.y, acc[5]);
    acc[6] = fmaf(v, f3.x, acc[6]); acc[7] = fmaf(v, f3.y, acc[7]);
}

__device__ __forceinline__ void bf16x8_to_f8(uint4 u, float* f) {
    __nv_bfloat162 b0 = *reinterpret_cast<const __nv_bfloat162*>(&u.x);
    __nv_bfloat162 b1 = *reinterpret_cast<const __nv_bfloat162*>(&u.y);
    __nv_bfloat162 b2 = *reinterpret_cast<const __nv_bfloat162*>(&u.z);
    __nv_bfloat162 b3 = *reinterpret_cast<const __nv_bfloat162*>(&u.w);
    float2 f0 = __bfloat1622float2(b0);
    float2 f1 = __bfloat1622float2(b1);
    float2 f2 = __bfloat1622float2(b2);
    float2 f3 = __bfloat1622float2(b3);
    f[0] = f0.x; f[1] = f0.y; f[2] = f1.x; f[3] = f1.y;
    f[4] = f2.x; f[5] = f2.y; f[6] = f3.x; f[7] = f3.y;
}

__device__ __forceinline__ uint4 pack_bf16x8(const float* a) {
    uint4 r;
    __nv_bfloat162 h0 = __floats2bfloat162_rn(a[0], a[1]);
    __nv_bfloat162 h1 = __floats2bfloat162_rn(a[2], a[3]);
    __nv_bfloat162 h2 = __floats2bfloat162_rn(a[4], a[5]);
    __nv_bfloat162 h3 = __floats2bfloat162_rn(a[6], a[7]);
    r.x = *reinterpret_cast<const unsigned*>(&h0);
    r.y = *reinterpret_cast<const unsigned*>(&h1);
    r.z = *reinterpret_cast<const unsigned*>(&h2);
    r.w = *reinterpret_cast<const unsigned*>(&h3);
    return r;
}

__device__ __forceinline__ uint2 pack_bf16x4(float4 a) {
    uint2 r;
    __nv_bfloat162 h0 = __floats2bfloat162_rn(a.x, a.y);
    __nv_bfloat162 h1 = __floats2bfloat162_rn(a.z, a.w);
    r.x = *reinterpret_cast<const unsigned*>(&h0);
    r.y = *reinterpret_cast<const unsigned*>(&h1);
    return r;
}

// ---------------- hist: edge histogram + blkdesc reset + W split ------------
__global__ void k_hist(const int* __restrict__ rows, const float4* __restrict__ W4) {
    int i = blockIdx.x * blockDim.x + threadIdx.x;
    if (i < SCAN_NB) g_blkdesc[i] = 0ull;
    if (i < 4096) {                    // one-time W hi/lo split (128x128 fp32)
        float4 w = W4[i];
        float wv[4] = {w.x, w.y, w.z, w.w};
        float hv[4], lv[4];
#pragma unroll
        for (int q = 0; q < 4; q++) {
            __nv_bfloat16 h = __float2bfloat16(wv[q]);
            hv[q] = __bfloat162float(h);
            lv[q] = wv[q] - hv[q];
        }
        reinterpret_cast<uint2*>(g_whi)[i] =
            pack_bf16x4(make_float4(hv[0], hv[1], hv[2], hv[3]));
        reinterpret_cast<uint2*>(g_wlo)[i] =
            pack_bf16x4(make_float4(lv[0], lv[1], lv[2], lv[3]));
    }
    if (i < NNZ) atomicAdd(&g_cnt[rows[i]], 1);   // g_cnt zero on entry (invariant)
}

// ---------------- single-pass scan (decoupled lookback) ----------------------
__global__ void __launch_bounds__(256) k_scan() {
    __shared__ int s[256];
    __shared__ int s_base;
    int tid = threadIdx.x, bid = blockIdx.x;
    int gid = bid * 256 + tid;
    int v = (gid < N_NODES) ? g_cnt[gid] : 0;
    if (gid < N_NODES) g_cnt[gid] = 0;            // restore zero invariant
    s[tid] = v;
    __syncthreads();
#pragma unroll
    for (int d = 1; d < 256; d <<= 1) {
        int t = (tid >= d) ? s[tid - d] : 0;
        __syncthreads();
        if (tid >= d) s[tid] += t;
        __syncthreads();
    }
    int incl = s[tid];
    int agg  = s[255];
    if (tid == 0) {
        unsigned long long w = ((bid == 0 ? 2ULL : 1ULL) << 32) | (unsigned)agg;
        atomicExch(&g_blkdesc[bid], w);
        if (bid == 0) s_base = 0;
    }
    if (bid > 0 && tid < 32) {
        int lane = tid;
        int exc = 0;
        int look = bid - 1;
        while (true) {
            int idx = look - lane;
            unsigned long long w;
            if (idx >= 0) {
                do { w = *(volatile unsigned long long*)&g_blkdesc[idx]; }
                while ((unsigned)(w >> 32) == 0u);
            } else {
                w = (2ULL << 32);
            }
            unsigned st = (unsigned)(w >> 32);
            int val = (int)(unsigned)w;
            unsigned bal = __ballot_sync(0xffffffffu, st == 2u);
            int first = __ffs(bal) - 1;
            int contrib = bal ? ((lane <= first) ? val : 0) : val;
#pragma unroll
            for (int o = 16; o; o >>= 1) contrib += __shfl_down_sync(0xffffffffu, contrib, o);
            contrib = __shfl_sync(0xffffffffu, contrib, 0);
            exc += contrib;
            if (bal) break;
            look -= 32;
        }
        if (lane == 0) {
            atomicExch(&g_blkdesc[bid], (2ULL << 32) | (unsigned)(exc + agg));
            s_base = exc;
        }
    }
    __syncthreads();
    int base = s_base;
    if (gid < N_NODES) {
        int o = base + incl - v;
        g_off[gid]  = o;
        g_fill[gid] = o;
    }
    if (gid == 0) g_off[N_NODES] = NNZ;
}

// ---------------- conv + scatter fused (post-scan) ---------------------------
__global__ void k_convscatter(const float4* __restrict__ ue, const float4* __restrict__ ie,
                              const int* __restrict__ rows, const int* __restrict__ cols,
                              const float* __restrict__ vals) {
    int i = blockIdx.x * blockDim.x + threadIdx.x;
    if (i < NNZ) {
        int p = atomicAdd(&g_fill[rows[i]], 1);
        g_edge[p] = make_uint2((unsigned)cols[i] * 16u, __float_as_uint(vals[i]));
    }
    if (i >= N_NODES * EMB4) return;
    int node = i >> 5;
    float4 v = (node < N_USERS) ? ue[i] : ie[i - N_USERS * EMB4];
    reinterpret_cast<uint2*>(g_embh[0])[i] = pack_bf16x4(v);
}

// ---------------- SpMM: warp/row, half-warp edge pairing (R7 core, frozen) --
__global__ void __launch_bounds__(256) k_spmm(int layer) {
    int gw   = (blockIdx.x * 256 + threadIdx.x) >> 5;
    int lane = threadIdx.x & 31;
    if (gw >= N_NODES) return;
    int half = lane >> 4;            // 0 | 1
    unsigned hl = lane & 15;         // uint4 granule within row
    const uint4* __restrict__ src = reinterpret_cast<const uint4*>(g_embh[layer]);
    int beg = g_off[gw], end = g_off[gw + 1];
    float acc[8] = {0.f, 0.f, 0.f, 0.f, 0.f, 0.f, 0.f, 0.f};
    int e = beg;
    for (; e + 8 <= end; e += 8) {   // 4 pairs = 8 edges per batch
        uint2 ed[4]; uint4 x[4];
#pragma unroll
        for (int p = 0; p < 4; p++) ed[p] = __ldg(&g_edge[e + 2 * p + half]);
#pragma unroll
        for (int p = 0; p < 4; p++) x[p] = src[ed[p].x + hl];
#pragma unroll
        for (int p = 0; p < 4; p++) fma_bf16x8(x[p], __uint_as_float(ed[p].y), acc);
    }
    for (; e + 2 <= end; e += 2) {
        uint2 ed = __ldg(&g_edge[e + half]);
        uint4 x  = src[ed.x + hl];
        fma_bf16x8(x, __uint_as_float(ed.y), acc);
    }
    if (e < end) {                   // single leftover edge: half 0 only
        uint2 ed = __ldg(&g_edge[e]);
        uint4 x  = src[ed.x + hl];
        float v  = half ? 0.f : __uint_as_float(ed.y);
        fma_bf16x8(x, v, acc);
    }
#pragma unroll
    for (int d = 0; d < 8; d++)
        acc[d] += __shfl_xor_sync(0xffffffffu, acc[d], 16);
    if (half == 0)
        reinterpret_cast<uint4*>(g_embh[layer + 1])[(unsigned)gw * 16u + hl] = pack_bf16x8(acc);
}

// ---------------- final: SpMM layer 2->3 fused with combine + outputs -------
#define O2_4 ((size_t)N_NODES * EMB4)                       // masked_user
#define O3_4 (O2_4 + (size_t)N_USERS * EMB4)                // predicted
#define O4_4 (O3_4 + (size_t)N_USERS * EMB4)                // mask

__global__ void __launch_bounds__(256) k_final(const float4* __restrict__ ue,
                                               const float4* __restrict__ ie,
                                               const float4* __restrict__ mask,
                                               float4* __restrict__ out) {
    int gw   = (blockIdx.x * 256 + threadIdx.x) >> 5;
    int lane = threadIdx.x & 31;
    if (gw >= N_NODES) return;
    int half = lane >> 4;
    unsigned hl = lane & 15;
    const uint4* __restrict__ src = reinterpret_cast<const uint4*>(g_embh[2]);
    int beg = g_off[gw], end = g_off[gw + 1];
    float acc[8] = {0.f, 0.f, 0.f, 0.f, 0.f, 0.f, 0.f, 0.f};
    int e = beg;
    for (; e + 8 <= end; e += 8) {
        uint2 ed[4]; uint4 x[4];
#pragma unroll
        for (int p = 0; p < 4; p++) ed[p] = __ldg(&g_edge[e + 2 * p + half]);
#pragma unroll
        for (int p = 0; p < 4; p++) x[p] = src[ed[p].x + hl];
#pragma unroll
        for (int p = 0; p < 4; p++) fma_bf16x8(x[p], __uint_as_float(ed[p].y), acc);
    }
    for (; e + 2 <= end; e += 2) {
        uint2 ed = __ldg(&g_edge[e + half]);
        uint4 x  = src[ed.x + hl];
        fma_bf16x8(x, __uint_as_float(ed.y), acc);
    }
    if (e < end) {
        uint2 ed = __ldg(&g_edge[e]);
        uint4 x  = src[ed.x + hl];
        float v  = half ? 0.f : __uint_as_float(ed.y);
        fma_bf16x8(x, v, acc);
    }
#pragma unroll
    for (int d = 0; d < 8; d++)
        acc[d] += __shfl_xor_sync(0xffffffffu, acc[d], 16);
    if (half) return;

    // lanes 0-15 own dims [8*hl, 8*hl+8) of the row
    unsigned g16 = (unsigned)gw * 16u + hl;       // uint4-granule index (bf16 rows)
    size_t   g32 = (size_t)gw * 32u + 2u * hl;    // float4-granule index (fp32 rows)
    float l0[8], l1[8], l2[8];
    {   // layer 0 exact from inputs
        float4 a0, a1;
        if (gw < N_USERS) { a0 = ue[g32]; a1 = ue[g32 + 1]; }
        else { size_t o = g32 - (size_t)N_USERS * 32u; a0 = ie[o]; a1 = ie[o + 1]; }
        l0[0]=a0.x; l0[1]=a0.y; l0[2]=a0.z; l0[3]=a0.w;
        l0[4]=a1.x; l0[5]=a1.y; l0[6]=a1.z; l0[7]=a1.w;
    }
    bf16x8_to_f8(reinterpret_cast<const uint4*>(g_embh[1])[g16], l1);
    bf16x8_to_f8(reinterpret_cast<const uint4*>(g_embh[2])[g16], l2);
    float comb[8];
#pragma unroll
    for (int d = 0; d < 8; d++)
        comb[d] = ALPHA * (l0[d] + l1[d] + l2[d] + acc[d]);
    float4 c0 = make_float4(comb[0], comb[1], comb[2], comb[3]);
    float4 c1 = make_float4(comb[4], comb[5], comb[6], comb[7]);
    out[g32]     = c0;                 // user_final / item_final (contiguous)
    out[g32 + 1] = c1;
    if (gw < N_USERS) {
        float4 m0 = mask[g32], m1 = mask[g32 + 1];
        out[O2_4 + g32]     = make_float4(c0.x*m0.x, c0.y*m0.y, c0.z*m0.z, c0.w*m0.w);
        out[O2_4 + g32 + 1] = make_float4(c1.x*m1.x, c1.y*m1.y, c1.z*m1.z, c1.w*m1.w);
        out[O4_4 + g32]     = m0;
        out[O4_4 + g32 + 1] = m1;
    }
}

// ---------------- GEMM: bf16-split tensor cores, fully smem-staged ----------
#define WLD 136   // bf16 leading dim in smem
#define CLD 132   // fp32 leading dim for C restage
__global__ void __launch_bounds__(256) k_gemm_tc(const float* __restrict__ A,
                                                 const float* __restrict__ bias,
                                                 float* __restrict__ C, int M) {
    extern __shared__ __align__(16) char smem_raw[];
    __nv_bfloat16* Whi = reinterpret_cast<__nv_bfloat16*>(smem_raw);
    __nv_bfloat16* Wlo = Whi + 128 * WLD;
    __nv_bfloat16* Ahi = Wlo + 128 * WLD;
    __nv_bfloat16* Alo = Ahi + 128 * WLD;
    int tid = threadIdx.x;
    int wid = tid >> 5;
    int m_base = blockIdx.x * 128;
    int wm = wid & 3;       // 32-row group
    int wn = wid >> 2;      // 64-col half

    // W hi/lo: straight uint4 copies from pre-split globals (8 per thread each)
#pragma unroll
    for (int p = 0; p < 8; p++) {
        int i = tid + p * 256;                // uint4 index, 0..2047
        int r = i >> 4, c8 = (i & 15) * 8;    // row, bf16 col
        int gidx = r * 16 + (i & 15);         // source granule (row-major, no pad)
        *reinterpret_cast<uint4*>(&Whi[r * WLD + c8]) = reinterpret_cast<const uint4*>(g_whi)[gidx];
        *reinterpret_cast<uint4*>(&Wlo[r * WLD + c8]) = reinterpret_cast<const uint4*>(g_wlo)[gidx];
    }
    // A fp32 -> hi/lo bf16 split into smem: 16 float4 per thread
#pragma unroll
    for (int p = 0; p < 16; p++) {
        int i = (tid + p * 256) * 4;          // float index within 128x128 tile
        int r = i >> 7, c = i & 127;
        int gm = m_base + r;
        float4 a = (gm < M) ? *reinterpret_cast<const float4*>(&A[(size_t)gm * 128 + c])
                            : make_float4(0.f, 0.f, 0.f, 0.f);
        float av[4] = {a.x, a.y, a.z, a.w};
#pragma unroll
        for (int q = 0; q < 4; q++) {
            __nv_bfloat16 h = __float2bfloat16(av[q]);
            Ahi[r * WLD + c + q] = h;
            Alo[r * WLD + c + q] = __float2bfloat16(av[q] - __bfloat162float(h));
        }
    }
    __syncthreads();

    wmma::fragment<wmma::accumulator, 16, 16, 16, float> acc[2][4];
#pragma unroll
    for (int im = 0; im < 2; im++)
#pragma unroll
        for (int jn = 0; jn < 4; jn++) wmma::fill_fragment(acc[im][jn], 0.0f);

#pragma unroll
    for (int k = 0; k < 128; k += 16) {
        wmma::fragment<wmma::matrix_a, 16, 16, 16, __nv_bfloat16, wmma::row_major> ahi[2], alo[2];
#pragma unroll
        for (int im = 0; im < 2; im++) {
            int row = wm * 32 + im * 16;
            wmma::load_matrix_sync(ahi[im], Ahi + row * WLD + k, WLD);
            wmma::load_matrix_sync(alo[im], Alo + row * WLD + k, WLD);
        }
#pragma unroll
        for (int jn = 0; jn < 4; jn++) {
            wmma::fragment<wmma::matrix_b, 16, 16, 16, __nv_bfloat16, wmma::row_major> bhi, blo;
            int bof = k * WLD + wn * 64 + jn * 16;
            wmma::load_matrix_sync(bhi, Whi + bof, WLD);
            wmma::load_matrix_sync(blo, Wlo + bof, WLD);
#pragma unroll
            for (int im = 0; im < 2; im++) {
                wmma::mma_sync(acc[im][jn], ahi[im], bhi, acc[im][jn]);
                wmma::mma_sync(acc[im][jn], ahi[im], blo, acc[im][jn]);
                wmma::mma_sync(acc[im][jn], alo[im], bhi, acc[im][jn]);
            }
        }
    }
    __syncthreads();   // done with smem tiles; reuse for C restage
    float* cs = reinterpret_cast<float*>(smem_raw);
#pragma unroll
    for (int im = 0; im < 2; im++)
#pragma unroll
        for (int jn = 0; jn < 4; jn++)
            wmma::store_matrix_sync(&cs[(wm * 32 + im * 16) * CLD + wn * 64 + jn * 16],
                                    acc[im][jn], CLD, wmma::mem_row_major);
    __syncthreads();
    // bias + relu + store: 128 rows x 32 float4, 16 per thread
#pragma unroll
    for (int q = 0; q < 16; q++) {
        int i = tid + q * 256;
        int r = i >> 5, c4 = (i & 31) * 4;
        int gm = m_base + r;
        if (gm < M) {
            float4 v  = *reinterpret_cast<float4*>(&cs[r * CLD + c4]);
            float4 b4 = *reinterpret_cast<const float4*>(&bias[c4]);
            v.x = fmaxf(v.x + b4.x, 0.f); v.y = fmaxf(v.y + b4.y, 0.f);
            v.z = fmaxf(v.z + b4.z, 0.f); v.w = fmaxf(v.w + b4.w, 0.f);
            *reinterpret_cast<float4*>(&C[(size_t)gm * 128 + c4]) = v;
        }
    }
}

// ---------------- launch -----------------------------------------------------
extern "C" void kernel_launch(void* const* d_in, const int* in_sizes, int n_in,
                              void* d_out, int out_size) {
    const float* ue   = (const float*)d_in[0];
    const float* ie   = (const float*)d_in[1];
    const int*   rows = (const int*)  d_in[2];
    const int*   cols = (const int*)  d_in[3];
    const float* vals = (const float*)d_in[4];
    const float* mask = (const float*)d_in[5];
    const float* W    = (const float*)d_in[6];
    const float* bias = (const float*)d_in[7];
    float* out = (float*)d_out;

    const int GEMM_SMEM = 4 * 128 * WLD * (int)sizeof(__nv_bfloat16); // 139264 B
    cudaFuncSetAttribute(k_gemm_tc, cudaFuncAttributeMaxDynamicSharedMemorySize, GEMM_SMEM);

    int nthr = N_NODES * EMB4;  // 4.8M
    k_hist<<<(NNZ + 255) / 256, 256>>>(rows, (const float4*)W);
    k_scan<<<SCAN_NB, 256>>>();
    k_convscatter<<<(nthr + 255) / 256, 256>>>((const float4*)ue, (const float4*)ie,
                                               rows, cols, vals);
    k_spmm<<<(N_NODES * 32 + 255) / 256, 256>>>(0);
    k_spmm<<<(N_NODES * 32 + 255) / 256, 256>>>(1);
    k_final<<<(N_NODES * 32 + 255) / 256, 256>>>((const float4*)ue, (const float4*)ie,
                                                 (const float4*)mask, (float4*)out);

    const float* Amasked = out + (size_t)N_NODES * EMB;   // masked_user (fp32)
    float* Cpred = out + (size_t)N_NODES * EMB + (size_t)N_USERS * EMB;
    k_gemm_tc<<<(N_USERS + 127) / 128, 256, GEMM_SMEM>>>(Amasked, bias, Cpred, N_USERS);
}